// round 10
// baseline (speedup 1.0000x reference)
#include <cuda_runtime.h>

#define TT   2048
#define BB   2048
#define HH   32
#define DF   8
#define DS   24
#define GPB  4                 // 4-batch groups per block
#define NW   (GPB * 3)         // 12 warps: (A,B,C) x 4 groups
#define NTHR (NW * 32)         // 384 threads
#define NBLK (BB / (GPB * 4))  // 128 blocks

typedef unsigned long long u64;

__device__ __forceinline__ u64 dup2(float w) {
    u64 d; asm("mov.b64 %0, {%1, %1};" : "=l"(d) : "f"(w)); return d;
}
__device__ __forceinline__ void unpack2(u64 v, float &a, float &b) {
    asm("mov.b64 {%0, %1}, %2;" : "=f"(a), "=f"(b) : "l"(v));
}
__device__ __forceinline__ void fma2(u64 &acc, u64 a, u64 b) {
    asm("fma.rn.f32x2 %0, %1, %2, %0;" : "+l"(acc) : "l"(a), "l"(b));
}
__device__ __forceinline__ u64 add2(u64 x, u64 y) {
    u64 r; asm("add.rn.f32x2 %0, %1, %2;" : "=l"(r) : "l"(x), "l"(y)); return r;
}
__device__ __forceinline__ float tanh_fast(float x) {
    float e = __expf(2.0f * x);
    return 1.0f - __fdividef(2.0f, e + 1.0f);
}

struct GroupSW {
    float4 hA[HH];                 // h_f  (warp A private; read only by A's tail)
    float4 hB[HH];                 // h_p  (warp B private)
    float4 sA[2][HH];              // h_s row 0, ping-pong
    float4 sB[2][HH];              // h_s row 1, ping-pong
    float4 sC[2][HH];              // h_s row 2, ping-pong
    float4 xA[DF], xB[DF];         // staged x_f / x_p
    float4 xC[DS];                 // staged x_s
};

__global__ void __launch_bounds__(NTHR, 1) chive_kernel(
    const float* __restrict__ frnn, const float* __restrict__ phrnn, const float* __restrict__ syl,
    const float* __restrict__ Wxf, const float* __restrict__ Whf, const float* __restrict__ bfv,
    const float* __restrict__ Wxp, const float* __restrict__ Whp, const float* __restrict__ bpv,
    const float* __restrict__ Wxs, const float* __restrict__ Whs, const float* __restrict__ bsv,
    const int* __restrict__ fclk, const int* __restrict__ pclk, const int* __restrict__ sfreq,
    float* __restrict__ out)
{
    __shared__ GroupSW sw[GPB];
    __shared__ unsigned char flags[TT];

    const int tid  = threadIdx.x;
    const int wid  = tid >> 5;
    const int lane = tid & 31;
    const int grp  = wid / 3;
    const int role = wid % 3;      // 0 = f-cell+row0, 1 = p-cell+row1, 2 = row2
    const int j    = lane;

    // ---- zero all state + staging (both s buffers) ----
    for (int i = tid; i < (int)(sizeof(GroupSW) / 4) * GPB; i += NTHR)
        ((float*)sw)[i] = 0.0f;

    // ---- warp-uniform update masks, depend only on t ----
    for (int t = tid; t < TT; t += NTHR) {
        int uf = ((t % (fclk[t] + 1)) == 0) ? 1 : 0;
        int up = ((t % (pclk[t] + 1)) == 0) ? 1 : 0;
        int us = (sfreq[t] == 1) ? 1 : 0;
        flags[t] = (unsigned char)(uf | (up << 1) | (us << 2));
    }
    __syncthreads();

    GroupSW& G = sw[grp];
    const int b0 = (blockIdx.x * GPB + grp) * 4;   // this group's 4 batch rows

    // ---- syl weight column j (all roles) ----
    float wsh[HH];
#pragma unroll
    for (int i = 0; i < HH; i++) wsh[i] = Whs[i * HH + j];
    const float bs_ = bsv[j];

    float4 (*sbuf)[HH] = (role == 0) ? G.sA : (role == 1) ? G.sB : G.sC;
    int sp = 0;                    // current valid s buffer

    // cached partials (all roles): S = s @ Wh_s   (s = 0 initially)
    u64 S0 = 0, S1 = 0;

    if (role < 2) {
        // ============ warp A / B: clockwork cell + its syl row ====================
        const float* xsrc = (role == 0) ? frnn : phrnn;
        const float* Wx   = (role == 0) ? Wxf  : Wxp;
        const float* Wh   = (role == 0) ? Whf  : Whp;
        const float* bv   = (role == 0) ? bfv  : bpv;
        float4* hst       = (role == 0) ? G.hA : G.hB;
        float4* xbuf      = (role == 0) ? G.xA : G.xB;
        const unsigned bit = 1u << role;

        float wx[DF], wh[HH], wsx[HH];
#pragma unroll
        for (int k = 0; k < DF; k++) wx[k] = Wx[k * HH + j];
#pragma unroll
        for (int i = 0; i < HH; i++) { wh[i] = Wh[i * HH + j]; wsx[i] = Wxs[i * HH + j]; }
        const float bc = bv[j];

        // cached partials: Hh = h@Wh (0), c = bs + h@Wx_s (bs)
        u64 Hh0 = 0, Hh1 = 0;
        u64 c0 = dup2(bs_), c1 = dup2(bs_);

        // staging: lane -> batch (lane>>3), feature (lane&7)
        const float* px = xsrc + (size_t)(b0 + (lane >> 3)) * DF + (lane & 7);
        float* xd = (float*)xbuf + (lane & 7) * 4 + (lane >> 3);
        const size_t str = (size_t)BB * DF;

        unsigned fl = flags[0];
        float v = (fl & bit) ? px[0] : 0.0f;
        for (int t = 0; t < TT; t++) {
            const unsigned fln = (t + 1 < TT) ? (unsigned)flags[t + 1] : 0u;

            if (fl & bit) {                    // ---- clockwork cell update ----
                xd[0] = v;                     // stage x[t]
                __syncwarp();                  // S1: x visible (also fences prior
                                               //     tail reads of h / x => WAR safe)
                u64 a = dup2(bc), b = dup2(bc);
                const ulonglong2* xv = (const ulonglong2*)xbuf;
#pragma unroll
                for (int k = 0; k < DF; k++) {
                    ulonglong2 x = xv[k]; u64 wd = dup2(wx[k]);
                    fma2(a, x.x, wd); fma2(b, x.y, wd);
                }
                u64 ra = add2(a, Hh0), rb = add2(b, Hh1);
                float q0, q1, q2, q3; unpack2(ra, q0, q1); unpack2(rb, q2, q3);
                float4 nf = make_float4(tanh_fast(q0), tanh_fast(q1),
                                        tanh_fast(q2), tanh_fast(q3));
                hst[j] = nf;                   // no pre-write sync needed (see S1)
                __syncwarp();                  // S2: new h visible to all lanes
                // tail: ONE 32-LDS stream over new h feeds BOTH Hh' and c'
                u64 ha = 0, hb = 0, hc = 0, hd = 0;      // Hh' chains
                u64 ca = dup2(bs_), cb = dup2(bs_), cc = 0, cd = 0;  // c' chains
                const ulonglong2* hv = (const ulonglong2*)hst;
#pragma unroll
                for (int i = 0; i < HH / 2; i++) {
                    ulonglong2 h = hv[i];
                    u64 w1 = dup2(wh[i]), w2 = dup2(wsx[i]);
                    fma2(ha, h.x, w1); fma2(hb, h.y, w1);
                    fma2(ca, h.x, w2); fma2(cb, h.y, w2);
                }
#pragma unroll
                for (int i = HH / 2; i < HH; i++) {
                    ulonglong2 h = hv[i];
                    u64 w1 = dup2(wh[i]), w2 = dup2(wsx[i]);
                    fma2(hc, h.x, w1); fma2(hd, h.y, w1);
                    fma2(cc, h.x, w2); fma2(cd, h.y, w2);
                }
                Hh0 = add2(ha, hc); Hh1 = add2(hb, hd);
                c0  = add2(ca, cc); c1  = add2(cb, cd);
            }
            if (fln & bit)                     // prefetch x[t+1] only if needed
                v = px[(size_t)(t + 1) * str];

            if (fl & 4) {                      // ---- syl row update ----
                // critical path: ZERO loads — tanh(c + S); write to alternate buf
                u64 ra = add2(c0, S0), rb = add2(c1, S1);
                float q0, q1, q2, q3; unpack2(ra, q0, q1); unpack2(rb, q2, q3);
                float4 n = make_float4(tanh_fast(q0), tanh_fast(q1),
                                       tanh_fast(q2), tanh_fast(q3));
                float4* snew = sbuf[sp ^ 1];
                snew[j] = n;                   // ping-pong: no WAR sync needed
                __syncwarp();                  // new s visible
                // tail: refresh S' = s_new @ Wh_s (32 LDS, 64 fma2)
                u64 e = 0, f = 0, g = 0, k2 = 0;
                const ulonglong2* rv = (const ulonglong2*)snew;
#pragma unroll
                for (int i = 0; i < HH / 2; i++) {
                    ulonglong2 h = rv[i]; u64 wd = dup2(wsh[i]);
                    fma2(e, h.x, wd); fma2(f, h.y, wd);
                }
#pragma unroll
                for (int i = HH / 2; i < HH; i++) {
                    ulonglong2 h = rv[i]; u64 wd = dup2(wsh[i]);
                    fma2(g, h.x, wd); fma2(k2, h.y, wd);
                }
                S0 = add2(e, g); S1 = add2(f, k2);
                sp ^= 1;
            }
            fl = fln;
        }
    } else {
        // ============ warp C: x_s-driven syl row ==================================
        float wsx[DS];
#pragma unroll
        for (int i = 0; i < DS; i++) wsx[i] = Wxs[i * HH + j];

        const int fl0 = lane, fl1 = lane + 32, fl2 = lane + 64;   // 96 scalars
        const float* p0 = syl + (size_t)(b0 + fl0 / 24) * DS + (fl0 % 24);
        const float* p1 = syl + (size_t)(b0 + fl1 / 24) * DS + (fl1 % 24);
        const float* p2 = syl + (size_t)(b0 + fl2 / 24) * DS + (fl2 % 24);
        float* d0 = (float*)G.xC + (fl0 % 24) * 4 + (fl0 / 24);
        float* d1 = (float*)G.xC + (fl1 % 24) * 4 + (fl1 / 24);
        float* d2 = (float*)G.xC + (fl2 % 24) * 4 + (fl2 / 24);
        const size_t str = (size_t)BB * DS;

        unsigned fl = flags[0];
        float v0 = 0.f, v1 = 0.f, v2 = 0.f;
        if (fl & 4) { v0 = p0[0]; v1 = p1[0]; v2 = p2[0]; }
        for (int t = 0; t < TT; t++) {
            const unsigned fln = (t + 1 < TT) ? (unsigned)flags[t + 1] : 0u;

            if (fl & 4) {
                d0[0] = v0; d1[0] = v1; d2[0] = v2;   // stage x_s[t]
                __syncwarp();                  // S1: x visible (fences prior tail too)
                // critical path: x-part (12 LDS, 48 fma2) + cached S
                u64 a = dup2(bs_), b = dup2(bs_), c = 0, d = 0;
                const ulonglong2* xv = (const ulonglong2*)G.xC;
#pragma unroll
                for (int i = 0; i < DS / 2; i++) {
                    ulonglong2 x = xv[i]; u64 wd = dup2(wsx[i]);
                    fma2(a, x.x, wd); fma2(b, x.y, wd);
                }
#pragma unroll
                for (int i = DS / 2; i < DS; i++) {
                    ulonglong2 x = xv[i]; u64 wd = dup2(wsx[i]);
                    fma2(c, x.x, wd); fma2(d, x.y, wd);
                }
                u64 ra = add2(add2(a, c), S0);
                u64 rb = add2(add2(b, d), S1);
                float q0, q1, q2, q3; unpack2(ra, q0, q1); unpack2(rb, q2, q3);
                float4 n = make_float4(tanh_fast(q0), tanh_fast(q1),
                                       tanh_fast(q2), tanh_fast(q3));
                float4* snew = sbuf[sp ^ 1];
                snew[j] = n;                   // ping-pong: WAR safe via S1
                __syncwarp();                  // new s visible
                // tail: refresh S'
                u64 e = 0, f = 0, g = 0, k2 = 0;
                const ulonglong2* rv = (const ulonglong2*)snew;
#pragma unroll
                for (int i = 0; i < HH / 2; i++) {
                    ulonglong2 h = rv[i]; u64 wd = dup2(wsh[i]);
                    fma2(e, h.x, wd); fma2(f, h.y, wd);
                }
#pragma unroll
                for (int i = HH / 2; i < HH; i++) {
                    ulonglong2 h = rv[i]; u64 wd = dup2(wsh[i]);
                    fma2(g, h.x, wd); fma2(k2, h.y, wd);
                }
                S0 = add2(e, g); S1 = add2(f, k2);
                sp ^= 1;
            }
            if (fln & 4) {                     // prefetch x_s[t+1] only if needed
                const size_t o = (size_t)(t + 1) * str;
                v0 = p0[o]; v1 = p1[o]; v2 = p2[o];
            }
            fl = fln;
        }
    }

    // ---- output: each warp writes its own h_s row (own lane's own writes) ----
    {
        float4 vv = sbuf[sp][j];
        out[((size_t)role * BB + b0 + 0) * HH + j] = vv.x;
        out[((size_t)role * BB + b0 + 1) * HH + j] = vv.y;
        out[((size_t)role * BB + b0 + 2) * HH + j] = vv.z;
        out[((size_t)role * BB + b0 + 3) * HH + j] = vv.w;
    }
}

extern "C" void kernel_launch(void* const* d_in, const int* in_sizes, int n_in,
                              void* d_out, int out_size)
{
    (void)in_sizes; (void)n_in; (void)out_size;
    chive_kernel<<<NBLK, NTHR>>>(
        (const float*)d_in[0],  (const float*)d_in[1],  (const float*)d_in[2],
        (const float*)d_in[3],  (const float*)d_in[4],  (const float*)d_in[5],
        (const float*)d_in[6],  (const float*)d_in[7],  (const float*)d_in[8],
        (const float*)d_in[9],  (const float*)d_in[10], (const float*)d_in[11],
        (const int*)d_in[12],   (const int*)d_in[13],   (const int*)d_in[14],
        (float*)d_out);
}

// round 14
// speedup vs baseline: 1.0524x; 1.0524x over previous
#include <cuda_runtime.h>

#define TT   2048
#define BB   2048
#define HH   32
#define DF   8
#define DS   24
#define GPB  4                 // 4-batch groups per block
#define NW   (GPB * 3)         // 12 warps: (A,B,C) x 4 groups
#define NTHR (NW * 32)         // 384 threads
#define NBLK (BB / (GPB * 4))  // 128 blocks

typedef unsigned long long u64;

__device__ __forceinline__ u64 dup2(float w) {
    u64 d; asm("mov.b64 %0, {%1, %1};" : "=l"(d) : "f"(w)); return d;
}
__device__ __forceinline__ void unpack2(u64 v, float &a, float &b) {
    asm("mov.b64 {%0, %1}, %2;" : "=f"(a), "=f"(b) : "l"(v));
}
__device__ __forceinline__ void fma2(u64 &acc, u64 a, u64 b) {
    asm("fma.rn.f32x2 %0, %1, %2, %0;" : "+l"(acc) : "l"(a), "l"(b));
}
__device__ __forceinline__ u64 add2(u64 x, u64 y) {
    u64 r; asm("add.rn.f32x2 %0, %1, %2;" : "=l"(r) : "l"(x), "l"(y)); return r;
}
// single-MUFU tanh (sm_75+): lat 16, 1 issue slot — replaces the
// EX2->RCP serial chain (~50 cyc, ~6 slots per value)
__device__ __forceinline__ float tanh_mufu(float x) {
    float y; asm("tanh.approx.f32 %0, %1;" : "=f"(y) : "f"(x)); return y;
}

struct GroupSW {
    float4 hA[HH];                 // h_f  (warp A private)
    float4 hB[HH];                 // h_p  (warp B private)
    float4 s0[HH], s1[HH], s2[HH]; // h_s rows (warp-private)
    float4 xA[DF], xB[DF];         // staged x_f / x_p
    float4 xC[DS];                 // staged x_s
};

__global__ void __launch_bounds__(NTHR, 1) chive_kernel(
    const float* __restrict__ frnn, const float* __restrict__ phrnn, const float* __restrict__ syl,
    const float* __restrict__ Wxf, const float* __restrict__ Whf, const float* __restrict__ bfv,
    const float* __restrict__ Wxp, const float* __restrict__ Whp, const float* __restrict__ bpv,
    const float* __restrict__ Wxs, const float* __restrict__ Whs, const float* __restrict__ bsv,
    const int* __restrict__ fclk, const int* __restrict__ pclk, const int* __restrict__ sfreq,
    float* __restrict__ out)
{
    __shared__ GroupSW sw[GPB];
    __shared__ unsigned char flags[TT];

    const int tid  = threadIdx.x;
    const int wid  = tid >> 5;
    const int lane = tid & 31;
    const int grp  = wid / 3;
    const int role = wid % 3;      // 0 = f-cell+row0, 1 = p-cell+row1, 2 = row2
    const int j    = lane;

    // ---- zero all state + staging ----
    for (int i = tid; i < (int)(sizeof(GroupSW) / 4) * GPB; i += NTHR)
        ((float*)sw)[i] = 0.0f;

    // ---- warp-uniform update masks, depend only on t ----
    for (int t = tid; t < TT; t += NTHR) {
        int uf = ((t % (fclk[t] + 1)) == 0) ? 1 : 0;
        int up = ((t % (pclk[t] + 1)) == 0) ? 1 : 0;
        int us = (sfreq[t] == 1) ? 1 : 0;
        flags[t] = (unsigned char)(uf | (up << 1) | (us << 2));
    }
    __syncthreads();

    GroupSW& G = sw[grp];
    const int b0 = (blockIdx.x * GPB + grp) * 4;   // this group's 4 batch rows

    // ---- syl weight column j (all roles) ----
    float wsh[HH];
#pragma unroll
    for (int i = 0; i < HH; i++) wsh[i] = Whs[i * HH + j];
    const float bs_ = bsv[j];

    float4* srow = (role == 0) ? G.s0 : (role == 1) ? G.s1 : G.s2;

    // cached partials (all roles): S = s @ Wh_s   (s = 0 initially)
    u64 S0 = 0, S1 = 0;

    if (role < 2) {
        // ============ warp A / B: clockwork cell + its syl row ====================
        const float* xsrc = (role == 0) ? frnn : phrnn;
        const float* Wx   = (role == 0) ? Wxf  : Wxp;
        const float* Wh   = (role == 0) ? Whf  : Whp;
        const float* bv   = (role == 0) ? bfv  : bpv;
        float4* hst       = (role == 0) ? G.hA : G.hB;
        float4* xbuf      = (role == 0) ? G.xA : G.xB;
        const unsigned bit = 1u << role;

        float wx[DF], wh[HH], wsx[HH];
#pragma unroll
        for (int k = 0; k < DF; k++) wx[k] = Wx[k * HH + j];
#pragma unroll
        for (int i = 0; i < HH; i++) { wh[i] = Wh[i * HH + j]; wsx[i] = Wxs[i * HH + j]; }
        const float bc = bv[j];

        // cached partials: Hh = h@Wh (0), c = bs + h@Wx_s (bs)
        u64 Hh0 = 0, Hh1 = 0;
        u64 c0 = dup2(bs_), c1 = dup2(bs_);

        // staging: lane -> batch (lane>>3), feature (lane&7)
        const float* px = xsrc + (size_t)(b0 + (lane >> 3)) * DF + (lane & 7);
        float* xd = (float*)xbuf + (lane & 7) * 4 + (lane >> 3);
        const size_t str = (size_t)BB * DF;

        unsigned fl = flags[0];
        float v = (fl & bit) ? px[0] : 0.0f;
        for (int t = 0; t < TT; t++) {
            const unsigned fln = (t + 1 < TT) ? (unsigned)flags[t + 1] : 0u;

            if (fl & bit) {                    // ---- clockwork cell update ----
                xd[0] = v;                     // stage x[t]
                __syncwarp();
                // critical path: x@Wx (8 LDS, 16 fma2) + cached Hh
                u64 a = dup2(bc), b = dup2(bc);
                const ulonglong2* xv = (const ulonglong2*)xbuf;
#pragma unroll
                for (int k = 0; k < DF; k++) {
                    ulonglong2 x = xv[k]; u64 wd = dup2(wx[k]);
                    fma2(a, x.x, wd); fma2(b, x.y, wd);
                }
                u64 ra = add2(a, Hh0), rb = add2(b, Hh1);
                float q0, q1, q2, q3; unpack2(ra, q0, q1); unpack2(rb, q2, q3);
                float4 nf = make_float4(tanh_mufu(q0), tanh_mufu(q1),
                                        tanh_mufu(q2), tanh_mufu(q3));
                __syncwarp();                  // WAR: x reads done before reuse; h write
                hst[j] = nf;
                __syncwarp();                  // new h visible to all lanes
                // tail: ONE 32-LDS stream over new h feeds BOTH Hh' and c'
                u64 ha = 0, hb = 0, hc = 0, hd = 0;      // Hh' chains
                u64 ca = dup2(bs_), cb = dup2(bs_), cc = 0, cd = 0;  // c' chains
                const ulonglong2* hv = (const ulonglong2*)hst;
#pragma unroll
                for (int i = 0; i < HH / 2; i++) {
                    ulonglong2 h = hv[i];
                    u64 w1 = dup2(wh[i]), w2 = dup2(wsx[i]);
                    fma2(ha, h.x, w1); fma2(hb, h.y, w1);
                    fma2(ca, h.x, w2); fma2(cb, h.y, w2);
                }
#pragma unroll
                for (int i = HH / 2; i < HH; i++) {
                    ulonglong2 h = hv[i];
                    u64 w1 = dup2(wh[i]), w2 = dup2(wsx[i]);
                    fma2(hc, h.x, w1); fma2(hd, h.y, w1);
                    fma2(cc, h.x, w2); fma2(cd, h.y, w2);
                }
                Hh0 = add2(ha, hc); Hh1 = add2(hb, hd);
                c0  = add2(ca, cc); c1  = add2(cb, cd);
            }
            if (fln & bit)                     // prefetch x[t+1] only if needed
                v = px[(size_t)(t + 1) * str];

            if (fl & 4) {                      // ---- syl row update ----
                // critical path: ZERO loads — tanh(c + S)
                u64 ra = add2(c0, S0), rb = add2(c1, S1);
                float q0, q1, q2, q3; unpack2(ra, q0, q1); unpack2(rb, q2, q3);
                float4 n = make_float4(tanh_mufu(q0), tanh_mufu(q1),
                                       tanh_mufu(q2), tanh_mufu(q3));
                __syncwarp();                  // WAR vs previous S' reads
                srow[j] = n;
                __syncwarp();                  // new s visible
                // tail: refresh S' = s_new @ Wh_s (32 LDS, 64 fma2)
                u64 e = 0, f = 0, g = 0, k2 = 0;
                const ulonglong2* rv = (const ulonglong2*)srow;
#pragma unroll
                for (int i = 0; i < HH / 2; i++) {
                    ulonglong2 h = rv[i]; u64 wd = dup2(wsh[i]);
                    fma2(e, h.x, wd); fma2(f, h.y, wd);
                }
#pragma unroll
                for (int i = HH / 2; i < HH; i++) {
                    ulonglong2 h = rv[i]; u64 wd = dup2(wsh[i]);
                    fma2(g, h.x, wd); fma2(k2, h.y, wd);
                }
                S0 = add2(e, g); S1 = add2(f, k2);
            }
            fl = fln;
        }
    } else {
        // ============ warp C: x_s-driven syl row ==================================
        float wsx[DS];
#pragma unroll
        for (int i = 0; i < DS; i++) wsx[i] = Wxs[i * HH + j];

        const int fl0 = lane, fl1 = lane + 32, fl2 = lane + 64;   // 96 scalars
        const float* p0 = syl + (size_t)(b0 + fl0 / 24) * DS + (fl0 % 24);
        const float* p1 = syl + (size_t)(b0 + fl1 / 24) * DS + (fl1 % 24);
        const float* p2 = syl + (size_t)(b0 + fl2 / 24) * DS + (fl2 % 24);
        float* d0 = (float*)G.xC + (fl0 % 24) * 4 + (fl0 / 24);
        float* d1 = (float*)G.xC + (fl1 % 24) * 4 + (fl1 / 24);
        float* d2 = (float*)G.xC + (fl2 % 24) * 4 + (fl2 / 24);
        const size_t str = (size_t)BB * DS;

        unsigned fl = flags[0];
        float v0 = 0.f, v1 = 0.f, v2 = 0.f;
        if (fl & 4) { v0 = p0[0]; v1 = p1[0]; v2 = p2[0]; }
        for (int t = 0; t < TT; t++) {
            const unsigned fln = (t + 1 < TT) ? (unsigned)flags[t + 1] : 0u;

            if (fl & 4) {
                d0[0] = v0; d1[0] = v1; d2[0] = v2;   // stage x_s[t]
                __syncwarp();
                // critical path: x-part (24 LDS iters, 48 fma2) + cached S
                u64 a = dup2(bs_), b = dup2(bs_), c = 0, d = 0;
                const ulonglong2* xv = (const ulonglong2*)G.xC;
#pragma unroll
                for (int i = 0; i < DS / 2; i++) {
                    ulonglong2 x = xv[i]; u64 wd = dup2(wsx[i]);
                    fma2(a, x.x, wd); fma2(b, x.y, wd);
                }
#pragma unroll
                for (int i = DS / 2; i < DS; i++) {
                    ulonglong2 x = xv[i]; u64 wd = dup2(wsx[i]);
                    fma2(c, x.x, wd); fma2(d, x.y, wd);
                }
                u64 ra = add2(add2(a, c), S0);
                u64 rb = add2(add2(b, d), S1);
                float q0, q1, q2, q3; unpack2(ra, q0, q1); unpack2(rb, q2, q3);
                float4 n = make_float4(tanh_mufu(q0), tanh_mufu(q1),
                                       tanh_mufu(q2), tanh_mufu(q3));
                __syncwarp();                  // x reads done; WAR vs prior S' reads
                srow[j] = n;
                __syncwarp();                  // new s visible
                // tail: refresh S'
                u64 e = 0, f = 0, g = 0, k2 = 0;
                const ulonglong2* rv = (const ulonglong2*)srow;
#pragma unroll
                for (int i = 0; i < HH / 2; i++) {
                    ulonglong2 h = rv[i]; u64 wd = dup2(wsh[i]);
                    fma2(e, h.x, wd); fma2(f, h.y, wd);
                }
#pragma unroll
                for (int i = HH / 2; i < HH; i++) {
                    ulonglong2 h = rv[i]; u64 wd = dup2(wsh[i]);
                    fma2(g, h.x, wd); fma2(k2, h.y, wd);
                }
                S0 = add2(e, g); S1 = add2(f, k2);
            }
            if (fln & 4) {                     // prefetch x_s[t+1] only if needed
                const size_t o = (size_t)(t + 1) * str;
                v0 = p0[o]; v1 = p1[o]; v2 = p2[o];
            }
            fl = fln;
        }
    }

    // ---- output: each warp writes its own h_s row ----
    {
        float4 vv = srow[j];
        out[((size_t)role * BB + b0 + 0) * HH + j] = vv.x;
        out[((size_t)role * BB + b0 + 1) * HH + j] = vv.y;
        out[((size_t)role * BB + b0 + 2) * HH + j] = vv.z;
        out[((size_t)role * BB + b0 + 3) * HH + j] = vv.w;
    }
}

extern "C" void kernel_launch(void* const* d_in, const int* in_sizes, int n_in,
                              void* d_out, int out_size)
{
    (void)in_sizes; (void)n_in; (void)out_size;
    chive_kernel<<<NBLK, NTHR>>>(
        (const float*)d_in[0],  (const float*)d_in[1],  (const float*)d_in[2],
        (const float*)d_in[3],  (const float*)d_in[4],  (const float*)d_in[5],
        (const float*)d_in[6],  (const float*)d_in[7],  (const float*)d_in[8],
        (const float*)d_in[9],  (const float*)d_in[10], (const float*)d_in[11],
        (const int*)d_in[12],   (const int*)d_in[13],   (const int*)d_in[14],
        (float*)d_out);
}

// round 15
// speedup vs baseline: 1.2154x; 1.1549x over previous
#include <cuda_runtime.h>

#define TT   2048
#define BB   2048
#define HH   32
#define DF   8
#define DS   24
#define GPB  4                 // 4-batch groups per block
#define NW   (GPB * 3)         // 12 warps: (A,B,C) x 4 groups
#define NTHR (NW * 32)         // 384 threads
#define NBLK (BB / (GPB * 4))  // 128 blocks

typedef unsigned long long u64;

__device__ __forceinline__ u64 dup2(float w) {
    u64 d; asm("mov.b64 %0, {%1, %1};" : "=l"(d) : "f"(w)); return d;
}
__device__ __forceinline__ void unpack2(u64 v, float &a, float &b) {
    asm("mov.b64 {%0, %1}, %2;" : "=f"(a), "=f"(b) : "l"(v));
}
__device__ __forceinline__ void fma2(u64 &acc, u64 a, u64 b) {
    asm("fma.rn.f32x2 %0, %1, %2, %0;" : "+l"(acc) : "l"(a), "l"(b));
}
__device__ __forceinline__ u64 add2(u64 x, u64 y) {
    u64 r; asm("add.rn.f32x2 %0, %1, %2;" : "=l"(r) : "l"(x), "l"(y)); return r;
}
__device__ __forceinline__ float tanh_mufu(float x) {
    float y; asm("tanh.approx.f32 %0, %1;" : "=f"(y) : "f"(x)); return y;
}

struct GroupSW {
    float4 hA[HH];                 // h_f  (warp A private)
    float4 hB[HH];                 // h_p  (warp B private)
    float4 s0[HH], s1[HH], s2[HH]; // h_s rows (warp-private)
    float4 xA[DF], xB[DF];         // staged x_f / x_p
    float4 xC[DS];                 // staged x_s
};

__global__ void __launch_bounds__(NTHR, 1) chive_kernel(
    const float* __restrict__ frnn, const float* __restrict__ phrnn, const float* __restrict__ syl,
    const float* __restrict__ Wxf, const float* __restrict__ Whf, const float* __restrict__ bfv,
    const float* __restrict__ Wxp, const float* __restrict__ Whp, const float* __restrict__ bpv,
    const float* __restrict__ Wxs, const float* __restrict__ Whs, const float* __restrict__ bsv,
    const int* __restrict__ fclk, const int* __restrict__ pclk, const int* __restrict__ sfreq,
    float* __restrict__ out)
{
    __shared__ GroupSW sw[GPB];
    __shared__ unsigned short lcA[TT + 1];   // t where f-cell fires, sentinel TT
    __shared__ unsigned short lcB[TT + 1];   // t where p-cell fires
    __shared__ unsigned short lsy[TT + 1];   // t where syl fires

    const int tid  = threadIdx.x;
    const int wid  = tid >> 5;
    const int lane = tid & 31;
    const int grp  = wid / 3;
    const int role = wid % 3;      // 0 = f-cell+row0, 1 = p-cell+row1, 2 = row2
    const int j    = lane;

    // ---- zero all state + staging ----
    for (int i = tid; i < (int)(sizeof(GroupSW) / 4) * GPB; i += NTHR)
        ((float*)sw)[i] = 0.0f;

    // ---- build event lists via warp ballot (warps 0,1,2) ----
    if (wid < 3) {
        unsigned short* lst = (wid == 0) ? lcA : (wid == 1) ? lcB : lsy;
        int cnt = 0;
        for (int base = 0; base < TT; base += 32) {
            int t = base + lane;
            bool act;
            if (wid == 0)      act = (t % (fclk[t] + 1)) == 0;
            else if (wid == 1) act = (t % (pclk[t] + 1)) == 0;
            else               act = (sfreq[t] == 1);
            unsigned bal = __ballot_sync(0xffffffffu, act);
            if (act) lst[cnt + __popc(bal & ((1u << lane) - 1))] = (unsigned short)t;
            cnt += __popc(bal);
        }
        if (lane == 0) lst[cnt] = (unsigned short)TT;   // sentinel
    }
    __syncthreads();

    GroupSW& G = sw[grp];
    const int b0 = (blockIdx.x * GPB + grp) * 4;   // this group's 4 batch rows

    // ---- syl weight column j (all roles) ----
    float wsh[HH];
#pragma unroll
    for (int i = 0; i < HH; i++) wsh[i] = Whs[i * HH + j];
    const float bs_ = bsv[j];

    float4* srow = (role == 0) ? G.s0 : (role == 1) ? G.s1 : G.s2;

    // cached partial (all roles): S = s @ Wh_s  (s = 0 initially)
    u64 S0 = 0, S1 = 0;

    if (role < 2) {
        // ============ warp A / B: clockwork cell + its syl row ====================
        const float* xsrc = (role == 0) ? frnn : phrnn;
        const float* Wx   = (role == 0) ? Wxf  : Wxp;
        const float* Wh   = (role == 0) ? Whf  : Whp;
        const float* bv   = (role == 0) ? bfv  : bpv;
        float4* hst       = (role == 0) ? G.hA : G.hB;
        float4* xbuf      = (role == 0) ? G.xA : G.xB;
        const unsigned short* lc = (role == 0) ? lcA : lcB;

        float wx[DF], wh[HH], wsx[HH];
#pragma unroll
        for (int k = 0; k < DF; k++) wx[k] = Wx[k * HH + j];
#pragma unroll
        for (int i = 0; i < HH; i++) { wh[i] = Wh[i * HH + j]; wsx[i] = Wxs[i * HH + j]; }
        const float bc = bv[j];

        // cached partials: Hh = h@Wh (0), c = bs + h@Wx_s (bs)
        u64 Hh0 = 0, Hh1 = 0;
        u64 c0 = dup2(bs_), c1 = dup2(bs_);

        // staging: lane -> batch (lane>>3), feature (lane&7)
        const float* px = xsrc + (size_t)(b0 + (lane >> 3)) * DF + (lane & 7);
        float* xd = (float*)xbuf + (lane & 7) * 4 + (lane >> 3);
        const size_t str = (size_t)BB * DF;

        int ic = 0, isx = 0;
        int tc = lc[0];
        int ts = lsy[0];
        float v = 0.0f;
        if (tc < TT) v = px[(size_t)tc * str];

        while (tc < TT || ts < TT) {
            if (tc <= ts) {                   // ---- cell event at t = tc ----
                xd[0] = v;                    // stage x[tc]
                __syncwarp();                 // entry sync: x visible; fences all
                                              // prior-event shared reads (WAR safe)
                u64 a = dup2(bc), b = dup2(bc);
                const ulonglong2* xv = (const ulonglong2*)xbuf;
#pragma unroll
                for (int k = 0; k < DF; k++) {
                    ulonglong2 x = xv[k]; u64 wd = dup2(wx[k]);
                    fma2(a, x.x, wd); fma2(b, x.y, wd);
                }
                u64 ra = add2(a, Hh0), rb = add2(b, Hh1);
                float q0, q1, q2, q3; unpack2(ra, q0, q1); unpack2(rb, q2, q3);
                float4 nf = make_float4(tanh_mufu(q0), tanh_mufu(q1),
                                        tanh_mufu(q2), tanh_mufu(q3));
                hst[j] = nf;                  // safe: x reads fenced by entry sync
                __syncwarp();                 // S2: new h visible
                // advance + prefetch next cell x NOW so LDG overlaps the tail
                int tcn = lc[++ic];
                if (tcn < TT) v = px[(size_t)tcn * str];
                // tail: ONE 32-LDS stream over new h feeds BOTH Hh' and c'
                u64 ha = 0, hb = 0, hc = 0, hd = 0;
                u64 ca = dup2(bs_), cb = dup2(bs_), cc = 0, cd = 0;
                const ulonglong2* hv = (const ulonglong2*)hst;
#pragma unroll
                for (int i = 0; i < HH / 2; i++) {
                    ulonglong2 h = hv[i];
                    u64 w1 = dup2(wh[i]), w2 = dup2(wsx[i]);
                    fma2(ha, h.x, w1); fma2(hb, h.y, w1);
                    fma2(ca, h.x, w2); fma2(cb, h.y, w2);
                }
#pragma unroll
                for (int i = HH / 2; i < HH; i++) {
                    ulonglong2 h = hv[i];
                    u64 w1 = dup2(wh[i]), w2 = dup2(wsx[i]);
                    fma2(hc, h.x, w1); fma2(hd, h.y, w1);
                    fma2(cc, h.x, w2); fma2(cd, h.y, w2);
                }
                Hh0 = add2(ha, hc); Hh1 = add2(hb, hd);
                c0  = add2(ca, cc); c1  = add2(cb, cd);

                if (tc == ts) {               // fused syl at same t (fresh c)
                    u64 sa = add2(c0, S0), sb = add2(c1, S1);
                    float p0_, p1_, p2_, p3_;
                    unpack2(sa, p0_, p1_); unpack2(sb, p2_, p3_);
                    float4 n = make_float4(tanh_mufu(p0_), tanh_mufu(p1_),
                                           tanh_mufu(p2_), tanh_mufu(p3_));
                    srow[j] = n;              // safe: prior srow reads fenced by S2
                    __syncwarp();             // new s visible
                    u64 e = 0, f = 0, g = 0, k2 = 0;
                    const ulonglong2* rv = (const ulonglong2*)srow;
#pragma unroll
                    for (int i = 0; i < HH / 2; i++) {
                        ulonglong2 h = rv[i]; u64 wd = dup2(wsh[i]);
                        fma2(e, h.x, wd); fma2(f, h.y, wd);
                    }
#pragma unroll
                    for (int i = HH / 2; i < HH; i++) {
                        ulonglong2 h = rv[i]; u64 wd = dup2(wsh[i]);
                        fma2(g, h.x, wd); fma2(k2, h.y, wd);
                    }
                    S0 = add2(e, g); S1 = add2(f, k2);
                    ts = lsy[++isx];
                }
                tc = tcn;
            } else {                          // ---- pure syl event at ts ----
                u64 sa = add2(c0, S0), sb = add2(c1, S1);
                float p0_, p1_, p2_, p3_;
                unpack2(sa, p0_, p1_); unpack2(sb, p2_, p3_);
                float4 n = make_float4(tanh_mufu(p0_), tanh_mufu(p1_),
                                       tanh_mufu(p2_), tanh_mufu(p3_));
                __syncwarp();                 // WAR vs prior S'-tail srow reads
                srow[j] = n;
                __syncwarp();                 // new s visible
                u64 e = 0, f = 0, g = 0, k2 = 0;
                const ulonglong2* rv = (const ulonglong2*)srow;
#pragma unroll
                for (int i = 0; i < HH / 2; i++) {
                    ulonglong2 h = rv[i]; u64 wd = dup2(wsh[i]);
                    fma2(e, h.x, wd); fma2(f, h.y, wd);
                }
#pragma unroll
                for (int i = HH / 2; i < HH; i++) {
                    ulonglong2 h = rv[i]; u64 wd = dup2(wsh[i]);
                    fma2(g, h.x, wd); fma2(k2, h.y, wd);
                }
                S0 = add2(e, g); S1 = add2(f, k2);
                ts = lsy[++isx];
            }
        }
    } else {
        // ============ warp C: x_s-driven syl row ==================================
        float wsx[DS];
#pragma unroll
        for (int i = 0; i < DS; i++) wsx[i] = Wxs[i * HH + j];

        const int fl0 = lane, fl1 = lane + 32, fl2 = lane + 64;   // 96 scalars
        const float* p0 = syl + (size_t)(b0 + fl0 / 24) * DS + (fl0 % 24);
        const float* p1 = syl + (size_t)(b0 + fl1 / 24) * DS + (fl1 % 24);
        const float* p2 = syl + (size_t)(b0 + fl2 / 24) * DS + (fl2 % 24);
        float* d0 = (float*)G.xC + (fl0 % 24) * 4 + (fl0 / 24);
        float* d1 = (float*)G.xC + (fl1 % 24) * 4 + (fl1 / 24);
        float* d2 = (float*)G.xC + (fl2 % 24) * 4 + (fl2 / 24);
        const size_t str = (size_t)BB * DS;

        int isx = 0;
        int ts = lsy[0];
        float v0 = 0.f, v1 = 0.f, v2 = 0.f;
        if (ts < TT) {
            size_t o = (size_t)ts * str;
            v0 = p0[o]; v1 = p1[o]; v2 = p2[o];
        }
        while (ts < TT) {
            d0[0] = v0; d1[0] = v1; d2[0] = v2;   // stage x_s[ts]
            __syncwarp();                          // entry sync (fences prior tail)
            u64 a = dup2(bs_), b = dup2(bs_), c = 0, d = 0;
            const ulonglong2* xv = (const ulonglong2*)G.xC;
#pragma unroll
            for (int i = 0; i < DS / 2; i++) {
                ulonglong2 x = xv[i]; u64 wd = dup2(wsx[i]);
                fma2(a, x.x, wd); fma2(b, x.y, wd);
            }
#pragma unroll
            for (int i = DS / 2; i < DS; i++) {
                ulonglong2 x = xv[i]; u64 wd = dup2(wsx[i]);
                fma2(c, x.x, wd); fma2(d, x.y, wd);
            }
            u64 ra = add2(add2(a, c), S0);
            u64 rb = add2(add2(b, d), S1);
            float q0, q1, q2, q3; unpack2(ra, q0, q1); unpack2(rb, q2, q3);
            float4 n = make_float4(tanh_mufu(q0), tanh_mufu(q1),
                                   tanh_mufu(q2), tanh_mufu(q3));
            srow[j] = n;                  // safe: prior srow reads fenced by entry sync
            __syncwarp();                 // new s + x-read WAR
            // advance + prefetch next event's x while the tail runs
            int tsn = lsy[++isx];
            if (tsn < TT) {
                size_t o = (size_t)tsn * str;
                v0 = p0[o]; v1 = p1[o]; v2 = p2[o];
            }
            // tail: refresh S'
            u64 e = 0, f = 0, g = 0, k2 = 0;
            const ulonglong2* rv = (const ulonglong2*)srow;
#pragma unroll
            for (int i = 0; i < HH / 2; i++) {
                ulonglong2 h = rv[i]; u64 wd = dup2(wsh[i]);
                fma2(e, h.x, wd); fma2(f, h.y, wd);
            }
#pragma unroll
            for (int i = HH / 2; i < HH; i++) {
                ulonglong2 h = rv[i]; u64 wd = dup2(wsh[i]);
                fma2(g, h.x, wd); fma2(k2, h.y, wd);
            }
            S0 = add2(e, g); S1 = add2(f, k2);
            ts = tsn;
        }
    }

    // ---- output: each warp writes its own h_s row ----
    {
        float4 vv = srow[j];
        out[((size_t)role * BB + b0 + 0) * HH + j] = vv.x;
        out[((size_t)role * BB + b0 + 1) * HH + j] = vv.y;
        out[((size_t)role * BB + b0 + 2) * HH + j] = vv.z;
        out[((size_t)role * BB + b0 + 3) * HH + j] = vv.w;
    }
}

extern "C" void kernel_launch(void* const* d_in, const int* in_sizes, int n_in,
                              void* d_out, int out_size)
{
    (void)in_sizes; (void)n_in; (void)out_size;
    chive_kernel<<<NBLK, NTHR>>>(
        (const float*)d_in[0],  (const float*)d_in[1],  (const float*)d_in[2],
        (const float*)d_in[3],  (const float*)d_in[4],  (const float*)d_in[5],
        (const float*)d_in[6],  (const float*)d_in[7],  (const float*)d_in[8],
        (const float*)d_in[9],  (const float*)d_in[10], (const float*)d_in[11],
        (const int*)d_in[12],   (const int*)d_in[13],   (const int*)d_in[14],
        (float*)d_out);
}

// round 16
// speedup vs baseline: 1.2246x; 1.0076x over previous
#include <cuda_runtime.h>

#define TT   2048
#define BB   2048
#define HH   32
#define DF   8
#define DS   24
#define GPB  4                 // 4-batch groups per block
#define NW   (GPB * 3)         // 12 warps: (A,B,C) x 4 groups
#define NTHR (NW * 32)         // 384 threads
#define NBLK (BB / (GPB * 4))  // 128 blocks

typedef unsigned long long u64;

__device__ __forceinline__ u64 dup2(float w) {
    u64 d; asm("mov.b64 %0, {%1, %1};" : "=l"(d) : "f"(w)); return d;
}
__device__ __forceinline__ void unpack2(u64 v, float &a, float &b) {
    asm("mov.b64 {%0, %1}, %2;" : "=f"(a), "=f"(b) : "l"(v));
}
__device__ __forceinline__ void fma2(u64 &acc, u64 a, u64 b) {
    asm("fma.rn.f32x2 %0, %1, %2, %0;" : "+l"(acc) : "l"(a), "l"(b));
}
__device__ __forceinline__ u64 add2(u64 x, u64 y) {
    u64 r; asm("add.rn.f32x2 %0, %1, %2;" : "=l"(r) : "l"(x), "l"(y)); return r;
}
__device__ __forceinline__ float tanh_mufu(float x) {
    float y; asm("tanh.approx.f32 %0, %1;" : "=f"(y) : "f"(x)); return y;
}

struct GroupSW {
    float4 hA[HH];                 // h_f  (warp A private)
    float4 hB[HH];                 // h_p  (warp B private)
    float4 sA[2][HH];              // h_s row 0, ping-pong
    float4 sB[2][HH];              // h_s row 1, ping-pong
    float4 sC[2][HH];              // h_s row 2, ping-pong
    float4 xA[DF], xB[DF];         // staged x_f / x_p
    float4 xC[DS];                 // staged x_s
};

__global__ void __launch_bounds__(NTHR, 1) chive_kernel(
    const float* __restrict__ frnn, const float* __restrict__ phrnn, const float* __restrict__ syl,
    const float* __restrict__ Wxf, const float* __restrict__ Whf, const float* __restrict__ bfv,
    const float* __restrict__ Wxp, const float* __restrict__ Whp, const float* __restrict__ bpv,
    const float* __restrict__ Wxs, const float* __restrict__ Whs, const float* __restrict__ bsv,
    const int* __restrict__ fclk, const int* __restrict__ pclk, const int* __restrict__ sfreq,
    float* __restrict__ out)
{
    __shared__ GroupSW sw[GPB];
    __shared__ unsigned short lcA[TT + 1];   // t where f-cell fires, sentinel TT
    __shared__ unsigned short lcB[TT + 1];   // t where p-cell fires
    __shared__ unsigned short lsy[TT + 1];   // t where syl fires

    const int tid  = threadIdx.x;
    const int wid  = tid >> 5;
    const int lane = tid & 31;
    const int grp  = wid / 3;
    const int role = wid % 3;      // 0 = f-cell+row0, 1 = p-cell+row1, 2 = row2
    const int j    = lane;

    // ---- zero all state + staging ----
    for (int i = tid; i < (int)(sizeof(GroupSW) / 4) * GPB; i += NTHR)
        ((float*)sw)[i] = 0.0f;

    // ---- build event lists via warp ballot (warps 0,1,2) ----
    if (wid < 3) {
        unsigned short* lst = (wid == 0) ? lcA : (wid == 1) ? lcB : lsy;
        int cnt = 0;
        for (int base = 0; base < TT; base += 32) {
            int t = base + lane;
            bool act;
            if (wid == 0)      act = (t % (fclk[t] + 1)) == 0;
            else if (wid == 1) act = (t % (pclk[t] + 1)) == 0;
            else               act = (sfreq[t] == 1);
            unsigned bal = __ballot_sync(0xffffffffu, act);
            if (act) lst[cnt + __popc(bal & ((1u << lane) - 1))] = (unsigned short)t;
            cnt += __popc(bal);
        }
        if (lane == 0) lst[cnt] = (unsigned short)TT;   // sentinel
    }
    __syncthreads();

    GroupSW& G = sw[grp];
    const int b0 = (blockIdx.x * GPB + grp) * 4;   // this group's 4 batch rows

    // ---- syl weight column j (all roles) ----
    float wsh[HH];
#pragma unroll
    for (int i = 0; i < HH; i++) wsh[i] = Whs[i * HH + j];
    const float bs_ = bsv[j];

    float4 (*sbuf)[HH] = (role == 0) ? G.sA : (role == 1) ? G.sB : G.sC;
    int sp = 0;                    // last-written s buffer

    // cached partial (all roles): S = s @ Wh_s  (s = 0 initially)
    u64 S0 = 0, S1 = 0;

    if (role < 2) {
        // ============ warp A / B: clockwork cell + its syl row ====================
        const float* xsrc = (role == 0) ? frnn : phrnn;
        const float* Wx   = (role == 0) ? Wxf  : Wxp;
        const float* Wh   = (role == 0) ? Whf  : Whp;
        const float* bv   = (role == 0) ? bfv  : bpv;
        float4* hst       = (role == 0) ? G.hA : G.hB;
        float4* xbuf      = (role == 0) ? G.xA : G.xB;
        const unsigned short* lc = (role == 0) ? lcA : lcB;

        float wx[DF], wh[HH], wsx[HH];
#pragma unroll
        for (int k = 0; k < DF; k++) wx[k] = Wx[k * HH + j];
#pragma unroll
        for (int i = 0; i < HH; i++) { wh[i] = Wh[i * HH + j]; wsx[i] = Wxs[i * HH + j]; }
        const float bc = bv[j];

        // cached partials: Hh = h@Wh (0), c = bs + h@Wx_s (bs)
        u64 Hh0 = 0, Hh1 = 0;
        u64 c0 = dup2(bs_), c1 = dup2(bs_);

        // staging: lane -> batch (lane>>3), feature (lane&7)
        const float* px = xsrc + (size_t)(b0 + (lane >> 3)) * DF + (lane & 7);
        float* xd = (float*)xbuf + (lane & 7) * 4 + (lane >> 3);
        const size_t str = (size_t)BB * DF;

        int ic = 0, isx = 0;
        int tc = lc[0];
        int ts = lsy[0];
        float v = 0.0f;
        if (tc < TT) v = px[(size_t)tc * str];

        while (tc < TT || ts < TT) {
            if (tc <= ts) {                   // ---- cell event at t = tc ----
                // hoist next-event index load: overlaps the whole event body
                const int tcn = lc[++ic];
                xd[0] = v;                    // stage x[tc]
                __syncwarp();                 // entry sync: x visible; fences all
                                              // prior-event shared reads (WAR safe)
                u64 a = dup2(bc), b = dup2(bc);
                const ulonglong2* xv = (const ulonglong2*)xbuf;
#pragma unroll
                for (int k = 0; k < DF; k++) {
                    ulonglong2 x = xv[k]; u64 wd = dup2(wx[k]);
                    fma2(a, x.x, wd); fma2(b, x.y, wd);
                }
                u64 ra = add2(a, Hh0), rb = add2(b, Hh1);
                float q0, q1, q2, q3; unpack2(ra, q0, q1); unpack2(rb, q2, q3);
                float4 nf = make_float4(tanh_mufu(q0), tanh_mufu(q1),
                                        tanh_mufu(q2), tanh_mufu(q3));
                hst[j] = nf;                  // safe: x reads fenced by entry sync
                __syncwarp();                 // S2: new h visible
                // prefetch next cell x NOW so LDG overlaps the tail
                if (tcn < TT) v = px[(size_t)tcn * str];
                // tail: ONE 32-LDS stream over new h feeds BOTH Hh' and c'
                u64 ha = 0, hb = 0, hc = 0, hd = 0;
                u64 ca = dup2(bs_), cb = dup2(bs_), cc = 0, cd = 0;
                const ulonglong2* hv = (const ulonglong2*)hst;
#pragma unroll
                for (int i = 0; i < HH / 2; i++) {
                    ulonglong2 h = hv[i];
                    u64 w1 = dup2(wh[i]), w2 = dup2(wsx[i]);
                    fma2(ha, h.x, w1); fma2(hb, h.y, w1);
                    fma2(ca, h.x, w2); fma2(cb, h.y, w2);
                }
#pragma unroll
                for (int i = HH / 2; i < HH; i++) {
                    ulonglong2 h = hv[i];
                    u64 w1 = dup2(wh[i]), w2 = dup2(wsx[i]);
                    fma2(hc, h.x, w1); fma2(hd, h.y, w1);
                    fma2(cc, h.x, w2); fma2(cd, h.y, w2);
                }
                Hh0 = add2(ha, hc); Hh1 = add2(hb, hd);
                c0  = add2(ca, cc); c1  = add2(cb, cd);

                if (tc == ts) {               // fused syl at same t (fresh c)
                    const int tsn = lsy[++isx];       // hoisted
                    u64 sa = add2(c0, S0), sb = add2(c1, S1);
                    float p0_, p1_, p2_, p3_;
                    unpack2(sa, p0_, p1_); unpack2(sb, p2_, p3_);
                    float4 n = make_float4(tanh_mufu(p0_), tanh_mufu(p1_),
                                           tanh_mufu(p2_), tanh_mufu(p3_));
                    float4* snew = sbuf[sp ^ 1];
                    snew[j] = n;              // ping-pong: prior reads hit old buf
                    __syncwarp();             // new s visible
                    u64 e = 0, f = 0, g = 0, k2 = 0;
                    const ulonglong2* rv = (const ulonglong2*)snew;
#pragma unroll
                    for (int i = 0; i < HH / 2; i++) {
                        ulonglong2 h = rv[i]; u64 wd = dup2(wsh[i]);
                        fma2(e, h.x, wd); fma2(f, h.y, wd);
                    }
#pragma unroll
                    for (int i = HH / 2; i < HH; i++) {
                        ulonglong2 h = rv[i]; u64 wd = dup2(wsh[i]);
                        fma2(g, h.x, wd); fma2(k2, h.y, wd);
                    }
                    S0 = add2(e, g); S1 = add2(f, k2);
                    sp ^= 1;
                    ts = tsn;
                }
                tc = tcn;
            } else {                          // ---- pure syl event at ts ----
                const int tsn = lsy[++isx];   // hoisted: overlaps event body
                u64 sa = add2(c0, S0), sb = add2(c1, S1);
                float p0_, p1_, p2_, p3_;
                unpack2(sa, p0_, p1_); unpack2(sb, p2_, p3_);
                float4 n = make_float4(tanh_mufu(p0_), tanh_mufu(p1_),
                                       tanh_mufu(p2_), tanh_mufu(p3_));
                float4* snew = sbuf[sp ^ 1];
                snew[j] = n;                  // ping-pong: no pre-write sync needed
                __syncwarp();                 // new s visible
                u64 e = 0, f = 0, g = 0, k2 = 0;
                const ulonglong2* rv = (const ulonglong2*)snew;
#pragma unroll
                for (int i = 0; i < HH / 2; i++) {
                    ulonglong2 h = rv[i]; u64 wd = dup2(wsh[i]);
                    fma2(e, h.x, wd); fma2(f, h.y, wd);
                }
#pragma unroll
                for (int i = HH / 2; i < HH; i++) {
                    ulonglong2 h = rv[i]; u64 wd = dup2(wsh[i]);
                    fma2(g, h.x, wd); fma2(k2, h.y, wd);
                }
                S0 = add2(e, g); S1 = add2(f, k2);
                sp ^= 1;
                ts = tsn;
            }
        }
    } else {
        // ============ warp C: x_s-driven syl row ==================================
        float wsx[DS];
#pragma unroll
        for (int i = 0; i < DS; i++) wsx[i] = Wxs[i * HH + j];

        const int fl0 = lane, fl1 = lane + 32, fl2 = lane + 64;   // 96 scalars
        const float* p0 = syl + (size_t)(b0 + fl0 / 24) * DS + (fl0 % 24);
        const float* p1 = syl + (size_t)(b0 + fl1 / 24) * DS + (fl1 % 24);
        const float* p2 = syl + (size_t)(b0 + fl2 / 24) * DS + (fl2 % 24);
        float* d0 = (float*)G.xC + (fl0 % 24) * 4 + (fl0 / 24);
        float* d1 = (float*)G.xC + (fl1 % 24) * 4 + (fl1 / 24);
        float* d2 = (float*)G.xC + (fl2 % 24) * 4 + (fl2 / 24);
        const size_t str = (size_t)BB * DS;

        int isx = 0;
        int ts = lsy[0];
        float v0 = 0.f, v1 = 0.f, v2 = 0.f;
        if (ts < TT) {
            size_t o = (size_t)ts * str;
            v0 = p0[o]; v1 = p1[o]; v2 = p2[o];
        }
        while (ts < TT) {
            const int tsn = lsy[++isx];       // hoisted: overlaps whole event
            d0[0] = v0; d1[0] = v1; d2[0] = v2;   // stage x_s[ts]
            __syncwarp();                          // entry sync (fences prior tail)
            u64 a = dup2(bs_), b = dup2(bs_), c = 0, d = 0;
            const ulonglong2* xv = (const ulonglong2*)G.xC;
#pragma unroll
            for (int i = 0; i < DS / 2; i++) {
                ulonglong2 x = xv[i]; u64 wd = dup2(wsx[i]);
                fma2(a, x.x, wd); fma2(b, x.y, wd);
            }
#pragma unroll
            for (int i = DS / 2; i < DS; i++) {
                ulonglong2 x = xv[i]; u64 wd = dup2(wsx[i]);
                fma2(c, x.x, wd); fma2(d, x.y, wd);
            }
            u64 ra = add2(add2(a, c), S0);
            u64 rb = add2(add2(b, d), S1);
            float q0, q1, q2, q3; unpack2(ra, q0, q1); unpack2(rb, q2, q3);
            float4 n = make_float4(tanh_mufu(q0), tanh_mufu(q1),
                                   tanh_mufu(q2), tanh_mufu(q3));
            float4* snew = sbuf[sp ^ 1];
            snew[j] = n;                  // ping-pong; prior tail read old buf
            __syncwarp();                 // new s + x-read WAR
            // prefetch next event's x while the tail runs
            if (tsn < TT) {
                size_t o = (size_t)tsn * str;
                v0 = p0[o]; v1 = p1[o]; v2 = p2[o];
            }
            // tail: refresh S'
            u64 e = 0, f = 0, g = 0, k2 = 0;
            const ulonglong2* rv = (const ulonglong2*)snew;
#pragma unroll
            for (int i = 0; i < HH / 2; i++) {
                ulonglong2 h = rv[i]; u64 wd = dup2(wsh[i]);
                fma2(e, h.x, wd); fma2(f, h.y, wd);
            }
#pragma unroll
            for (int i = HH / 2; i < HH; i++) {
                ulonglong2 h = rv[i]; u64 wd = dup2(wsh[i]);
                fma2(g, h.x, wd); fma2(k2, h.y, wd);
            }
            S0 = add2(e, g); S1 = add2(f, k2);
            sp ^= 1;
            ts = tsn;
        }
    }

    // ---- output: each warp writes its own h_s row (lane reads its own writes) ----
    {
        float4 vv = sbuf[sp][j];
        out[((size_t)role * BB + b0 + 0) * HH + j] = vv.x;
        out[((size_t)role * BB + b0 + 1) * HH + j] = vv.y;
        out[((size_t)role * BB + b0 + 2) * HH + j] = vv.z;
        out[((size_t)role * BB + b0 + 3) * HH + j] = vv.w;
    }
}

extern "C" void kernel_launch(void* const* d_in, const int* in_sizes, int n_in,
                              void* d_out, int out_size)
{
    (void)in_sizes; (void)n_in; (void)out_size;
    chive_kernel<<<NBLK, NTHR>>>(
        (const float*)d_in[0],  (const float*)d_in[1],  (const float*)d_in[2],
        (const float*)d_in[3],  (const float*)d_in[4],  (const float*)d_in[5],
        (const float*)d_in[6],  (const float*)d_in[7],  (const float*)d_in[8],
        (const float*)d_in[9],  (const float*)d_in[10], (const float*)d_in[11],
        (const int*)d_in[12],   (const int*)d_in[13],   (const int*)d_in[14],
        (float*)d_out);
}

// round 17
// speedup vs baseline: 1.2328x; 1.0067x over previous
#include <cuda_runtime.h>

#define TT   2048
#define BB   2048
#define HH   32
#define DF   8
#define DS   24
#define GPB  4                 // 4-batch groups per block
#define NW   (GPB * 3)         // 12 warps: (A,B,C) x 4 groups
#define NTHR (NW * 32)         // 384 threads
#define NBLK (BB / (GPB * 4))  // 128 blocks

typedef unsigned long long u64;

__device__ __forceinline__ u64 dup2(float w) {
    u64 d; asm("mov.b64 %0, {%1, %1};" : "=l"(d) : "f"(w)); return d;
}
__device__ __forceinline__ void unpack2(u64 v, float &a, float &b) {
    asm("mov.b64 {%0, %1}, %2;" : "=f"(a), "=f"(b) : "l"(v));
}
__device__ __forceinline__ void fma2(u64 &acc, u64 a, u64 b) {
    asm("fma.rn.f32x2 %0, %1, %2, %0;" : "+l"(acc) : "l"(a), "l"(b));
}
__device__ __forceinline__ u64 add2(u64 x, u64 y) {
    u64 r; asm("add.rn.f32x2 %0, %1, %2;" : "=l"(r) : "l"(x), "l"(y)); return r;
}
__device__ __forceinline__ float tanh_mufu(float x) {
    float y; asm("tanh.approx.f32 %0, %1;" : "=f"(y) : "f"(x)); return y;
}

struct GroupSW {
    float4 hA[HH];                 // h_f  (warp A private)
    float4 hB[HH];                 // h_p  (warp B private)
    float4 sA[2][HH];              // h_s row 0, ping-pong
    float4 sB[2][HH];              // h_s row 1, ping-pong
    float4 sC[2][HH];              // h_s row 2, ping-pong
    float4 xA[2][DF], xB[2][DF];   // staged x_f / x_p, ping-pong per event
    float4 xC[2][DS];              // staged x_s, ping-pong per event
};

__global__ void __launch_bounds__(NTHR, 1) chive_kernel(
    const float* __restrict__ frnn, const float* __restrict__ phrnn, const float* __restrict__ syl,
    const float* __restrict__ Wxf, const float* __restrict__ Whf, const float* __restrict__ bfv,
    const float* __restrict__ Wxp, const float* __restrict__ Whp, const float* __restrict__ bpv,
    const float* __restrict__ Wxs, const float* __restrict__ Whs, const float* __restrict__ bsv,
    const int* __restrict__ fclk, const int* __restrict__ pclk, const int* __restrict__ sfreq,
    float* __restrict__ out)
{
    __shared__ GroupSW sw[GPB];
    __shared__ unsigned short lcA[TT + 2];   // t where f-cell fires, 2 sentinels
    __shared__ unsigned short lcB[TT + 2];
    __shared__ unsigned short lsy[TT + 2];

    const int tid  = threadIdx.x;
    const int wid  = tid >> 5;
    const int lane = tid & 31;
    const int grp  = wid / 3;
    const int role = wid % 3;      // 0 = f-cell+row0, 1 = p-cell+row1, 2 = row2
    const int j    = lane;

    // ---- zero all state + staging ----
    for (int i = tid; i < (int)(sizeof(GroupSW) / 4) * GPB; i += NTHR)
        ((float*)sw)[i] = 0.0f;

    // ---- build event lists via warp ballot (warps 0,1,2) ----
    if (wid < 3) {
        unsigned short* lst = (wid == 0) ? lcA : (wid == 1) ? lcB : lsy;
        int cnt = 0;
        for (int base = 0; base < TT; base += 32) {
            int t = base + lane;
            bool act;
            if (wid == 0)      act = (t % (fclk[t] + 1)) == 0;
            else if (wid == 1) act = (t % (pclk[t] + 1)) == 0;
            else               act = (sfreq[t] == 1);
            unsigned bal = __ballot_sync(0xffffffffu, act);
            if (act) lst[cnt + __popc(bal & ((1u << lane) - 1))] = (unsigned short)t;
            cnt += __popc(bal);
        }
        if (lane == 0) { lst[cnt] = (unsigned short)TT; lst[cnt + 1] = (unsigned short)TT; }
    }
    __syncthreads();

    GroupSW& G = sw[grp];
    const int b0 = (blockIdx.x * GPB + grp) * 4;   // this group's 4 batch rows

    // ---- syl weight column j (all roles) ----
    float wsh[HH];
#pragma unroll
    for (int i = 0; i < HH; i++) wsh[i] = Whs[i * HH + j];
    const float bs_ = bsv[j];

    float4 (*sbuf)[HH] = (role == 0) ? G.sA : (role == 1) ? G.sB : G.sC;
    int sp = 0;                    // last-written s buffer

    // cached partial (all roles): S = s @ Wh_s  (s = 0 initially)
    u64 S0 = 0, S1 = 0;

    if (role < 2) {
        // ============ warp A / B: clockwork cell + its syl row ====================
        const float* xsrc = (role == 0) ? frnn : phrnn;
        const float* Wx   = (role == 0) ? Wxf  : Wxp;
        const float* Wh   = (role == 0) ? Whf  : Whp;
        const float* bv   = (role == 0) ? bfv  : bpv;
        float4* hst       = (role == 0) ? G.hA : G.hB;
        float4 (*xbuf)[DF] = (role == 0) ? G.xA : G.xB;
        const unsigned short* lc = (role == 0) ? lcA : lcB;

        float wx[DF], wh[HH], wsx[HH];
#pragma unroll
        for (int k = 0; k < DF; k++) wx[k] = Wx[k * HH + j];
#pragma unroll
        for (int i = 0; i < HH; i++) { wh[i] = Wh[i * HH + j]; wsx[i] = Wxs[i * HH + j]; }
        const float bc = bv[j];

        // cached partials: Hh = h@Wh (0), c = bs + h@Wx_s (bs), Xc = bc + x@Wx
        u64 Hh0 = 0, Hh1 = 0;
        u64 c0 = dup2(bs_), c1 = dup2(bs_);
        u64 Xc0 = dup2(bc), Xc1 = dup2(bc);

        // staging: lane -> batch (lane>>3), feature (lane&7); 32 floats per buffer
        const float* px = xsrc + (size_t)(b0 + (lane >> 3)) * DF + (lane & 7);
        float* xd = (float*)xbuf + (lane & 7) * 4 + (lane >> 3);
        const size_t str = (size_t)BB * DF;

        int ic = 0, isx = 0;
        int tc = lc[0];
        int ts = lsy[0];
        int xq = 0;
        float v = 0.0f;

        if (tc < TT) {                        // pre-compute Xc for first cell event
            v = px[(size_t)tc * str];
            xd[0] = v;                        // buffer 0
            __syncwarp();
            u64 a = dup2(bc), b = dup2(bc);
            const ulonglong2* xv = (const ulonglong2*)xbuf[0];
#pragma unroll
            for (int k = 0; k < DF; k++) {
                ulonglong2 x = xv[k]; u64 wd = dup2(wx[k]);
                fma2(a, x.x, wd); fma2(b, x.y, wd);
            }
            Xc0 = a; Xc1 = b;
            const int t1 = lc[1];
            if (t1 < TT) v = px[(size_t)t1 * str];   // in flight for event 1
        }

        while (tc < TT || ts < TT) {
            if (tc <= ts) {                   // ---- cell event at t = tc ----
                const int tcn = lc[++ic];
                const int tc2 = lc[ic + 1];
                // front: cached Xc + cached Hh -> tanh -> h
                u64 ra = add2(Xc0, Hh0), rb = add2(Xc1, Hh1);
                float q0, q1, q2, q3; unpack2(ra, q0, q1); unpack2(rb, q2, q3);
                float4 nf = make_float4(tanh_mufu(q0), tanh_mufu(q1),
                                        tanh_mufu(q2), tanh_mufu(q3));
                hst[j] = nf;
                const int xqn = xq ^ 1;
                xd[xqn * 32] = v;             // stage x[tcn] (ping-pong buffer)
                __syncwarp();                 // h + staged x visible
                if (tc2 < TT) v = px[(size_t)tc2 * str];  // depth-2 prefetch
                // tail 1: ONE 32-LDS stream over new h feeds BOTH Hh' and c'
                u64 ha = 0, hb = 0, hc = 0, hd = 0;
                u64 ca = dup2(bs_), cb = dup2(bs_), cc = 0, cd = 0;
                const ulonglong2* hv = (const ulonglong2*)hst;
#pragma unroll
                for (int i = 0; i < HH / 2; i++) {
                    ulonglong2 h = hv[i];
                    u64 w1 = dup2(wh[i]), w2 = dup2(wsx[i]);
                    fma2(ha, h.x, w1); fma2(hb, h.y, w1);
                    fma2(ca, h.x, w2); fma2(cb, h.y, w2);
                }
#pragma unroll
                for (int i = HH / 2; i < HH; i++) {
                    ulonglong2 h = hv[i];
                    u64 w1 = dup2(wh[i]), w2 = dup2(wsx[i]);
                    fma2(hc, h.x, w1); fma2(hd, h.y, w1);
                    fma2(cc, h.x, w2); fma2(cd, h.y, w2);
                }
                Hh0 = add2(ha, hc); Hh1 = add2(hb, hd);
                c0  = add2(ca, cc); c1  = add2(cb, cd);

                if (tc == ts) {               // fused syl at same t (fresh c)
                    const int tsn = lsy[++isx];
                    u64 sa = add2(c0, S0), sb = add2(c1, S1);
                    float p0_, p1_, p2_, p3_;
                    unpack2(sa, p0_, p1_); unpack2(sb, p2_, p3_);
                    float4 n = make_float4(tanh_mufu(p0_), tanh_mufu(p1_),
                                           tanh_mufu(p2_), tanh_mufu(p3_));
                    float4* snew = sbuf[sp ^ 1];
                    snew[j] = n;
                    __syncwarp();
                    u64 e = 0, f = 0, g = 0, k2 = 0;
                    const ulonglong2* rv = (const ulonglong2*)snew;
#pragma unroll
                    for (int i = 0; i < HH / 2; i++) {
                        ulonglong2 h = rv[i]; u64 wd = dup2(wsh[i]);
                        fma2(e, h.x, wd); fma2(f, h.y, wd);
                    }
#pragma unroll
                    for (int i = HH / 2; i < HH; i++) {
                        ulonglong2 h = rv[i]; u64 wd = dup2(wsh[i]);
                        fma2(g, h.x, wd); fma2(k2, h.y, wd);
                    }
                    S0 = add2(e, g); S1 = add2(f, k2);
                    sp ^= 1;
                    ts = tsn;
                }
                // tail 2: Xc for next cell event (from just-staged x buffer)
                {
                    u64 a = dup2(bc), b = dup2(bc);
                    const ulonglong2* xv = (const ulonglong2*)xbuf[xqn];
#pragma unroll
                    for (int k = 0; k < DF; k++) {
                        ulonglong2 x = xv[k]; u64 wd = dup2(wx[k]);
                        fma2(a, x.x, wd); fma2(b, x.y, wd);
                    }
                    Xc0 = a; Xc1 = b;
                }
                xq = xqn;
                tc = tcn;
            } else {                          // ---- pure syl event at ts ----
                const int tsn = lsy[++isx];
                u64 sa = add2(c0, S0), sb = add2(c1, S1);
                float p0_, p1_, p2_, p3_;
                unpack2(sa, p0_, p1_); unpack2(sb, p2_, p3_);
                float4 n = make_float4(tanh_mufu(p0_), tanh_mufu(p1_),
                                       tanh_mufu(p2_), tanh_mufu(p3_));
                float4* snew = sbuf[sp ^ 1];
                snew[j] = n;
                __syncwarp();
                u64 e = 0, f = 0, g = 0, k2 = 0;
                const ulonglong2* rv = (const ulonglong2*)snew;
#pragma unroll
                for (int i = 0; i < HH / 2; i++) {
                    ulonglong2 h = rv[i]; u64 wd = dup2(wsh[i]);
                    fma2(e, h.x, wd); fma2(f, h.y, wd);
                }
#pragma unroll
                for (int i = HH / 2; i < HH; i++) {
                    ulonglong2 h = rv[i]; u64 wd = dup2(wsh[i]);
                    fma2(g, h.x, wd); fma2(k2, h.y, wd);
                }
                S0 = add2(e, g); S1 = add2(f, k2);
                sp ^= 1;
                ts = tsn;
            }
        }
    } else {
        // ============ warp C: x_s-driven syl row ==================================
        float wsx[DS];
#pragma unroll
        for (int i = 0; i < DS; i++) wsx[i] = Wxs[i * HH + j];

        const int fl0 = lane, fl1 = lane + 32, fl2 = lane + 64;   // 96 scalars
        const float* p0 = syl + (size_t)(b0 + fl0 / 24) * DS + (fl0 % 24);
        const float* p1 = syl + (size_t)(b0 + fl1 / 24) * DS + (fl1 % 24);
        const float* p2 = syl + (size_t)(b0 + fl2 / 24) * DS + (fl2 % 24);
        float* d0 = (float*)G.xC + (fl0 % 24) * 4 + (fl0 / 24);
        float* d1 = (float*)G.xC + (fl1 % 24) * 4 + (fl1 / 24);
        float* d2 = (float*)G.xC + (fl2 % 24) * 4 + (fl2 / 24);
        const size_t str = (size_t)BB * DS;

        int isx = 0;
        int ts = lsy[0];
        int xq = 0;
        u64 Xs0 = dup2(bs_), Xs1 = dup2(bs_);
        float v0 = 0.f, v1 = 0.f, v2 = 0.f;

        if (ts < TT) {                        // pre-compute Xs for first event
            size_t o = (size_t)ts * str;
            v0 = p0[o]; v1 = p1[o]; v2 = p2[o];
            d0[0] = v0; d1[0] = v1; d2[0] = v2;   // buffer 0
            __syncwarp();
            u64 a = dup2(bs_), b = dup2(bs_), c = 0, d = 0;
            const ulonglong2* xv = (const ulonglong2*)G.xC[0];
#pragma unroll
            for (int i = 0; i < DS / 2; i++) {
                ulonglong2 x = xv[i]; u64 wd = dup2(wsx[i]);
                fma2(a, x.x, wd); fma2(b, x.y, wd);
            }
#pragma unroll
            for (int i = DS / 2; i < DS; i++) {
                ulonglong2 x = xv[i]; u64 wd = dup2(wsx[i]);
                fma2(c, x.x, wd); fma2(d, x.y, wd);
            }
            Xs0 = add2(a, c); Xs1 = add2(b, d);
            const int t1 = lsy[1];
            if (t1 < TT) {
                o = (size_t)t1 * str;
                v0 = p0[o]; v1 = p1[o]; v2 = p2[o];
            }
        }

        while (ts < TT) {
            const int tsn = lsy[++isx];
            const int ts2 = lsy[isx + 1];
            // front: cached Xs + cached S -> tanh -> s (ZERO loads)
            u64 ra = add2(Xs0, S0), rb = add2(Xs1, S1);
            float q0, q1, q2, q3; unpack2(ra, q0, q1); unpack2(rb, q2, q3);
            float4 n = make_float4(tanh_mufu(q0), tanh_mufu(q1),
                                   tanh_mufu(q2), tanh_mufu(q3));
            float4* snew = sbuf[sp ^ 1];
            snew[j] = n;
            const int xqn = xq ^ 1;
            d0[xqn * 96] = v0; d1[xqn * 96] = v1; d2[xqn * 96] = v2;  // stage x[tsn]
            __syncwarp();                 // s + staged x visible
            if (ts2 < TT) {               // depth-2 prefetch
                size_t o = (size_t)ts2 * str;
                v0 = p0[o]; v1 = p1[o]; v2 = p2[o];
            }
            // tail: S' refresh (32 LDS) + Xs for next event (24 LDS)
            u64 e = 0, f = 0, g = 0, k2 = 0;
            const ulonglong2* rv = (const ulonglong2*)snew;
#pragma unroll
            for (int i = 0; i < HH / 2; i++) {
                ulonglong2 h = rv[i]; u64 wd = dup2(wsh[i]);
                fma2(e, h.x, wd); fma2(f, h.y, wd);
            }
#pragma unroll
            for (int i = HH / 2; i < HH; i++) {
                ulonglong2 h = rv[i]; u64 wd = dup2(wsh[i]);
                fma2(g, h.x, wd); fma2(k2, h.y, wd);
            }
            S0 = add2(e, g); S1 = add2(f, k2);
            {
                u64 a = dup2(bs_), b = dup2(bs_), c = 0, d = 0;
                const ulonglong2* xv = (const ulonglong2*)G.xC[xqn];
#pragma unroll
                for (int i = 0; i < DS / 2; i++) {
                    ulonglong2 x = xv[i]; u64 wd = dup2(wsx[i]);
                    fma2(a, x.x, wd); fma2(b, x.y, wd);
                }
#pragma unroll
                for (int i = DS / 2; i < DS; i++) {
                    ulonglong2 x = xv[i]; u64 wd = dup2(wsx[i]);
                    fma2(c, x.x, wd); fma2(d, x.y, wd);
                }
                Xs0 = add2(a, c); Xs1 = add2(b, d);
            }
            sp ^= 1;
            xq = xqn;
            ts = tsn;
        }
    }

    // ---- output: each warp writes its own h_s row (lane reads its own writes) ----
    {
        float4 vv = sbuf[sp][j];
        out[((size_t)role * BB + b0 + 0) * HH + j] = vv.x;
        out[((size_t)role * BB + b0 + 1) * HH + j] = vv.y;
        out[((size_t)role * BB + b0 + 2) * HH + j] = vv.z;
        out[((size_t)role * BB + b0 + 3) * HH + j] = vv.w;
    }
}

extern "C" void kernel_launch(void* const* d_in, const int* in_sizes, int n_in,
                              void* d_out, int out_size)
{
    (void)in_sizes; (void)n_in; (void)out_size;
    chive_kernel<<<NBLK, NTHR>>>(
        (const float*)d_in[0],  (const float*)d_in[1],  (const float*)d_in[2],
        (const float*)d_in[3],  (const float*)d_in[4],  (const float*)d_in[5],
        (const float*)d_in[6],  (const float*)d_in[7],  (const float*)d_in[8],
        (const float*)d_in[9],  (const float*)d_in[10], (const float*)d_in[11],
        (const int*)d_in[12],   (const int*)d_in[13],   (const int*)d_in[14],
        (float*)d_out);
}